// round 17
// baseline (speedup 1.0000x reference)
#include <cuda_runtime.h>
#include <cuda_fp16.h>
#include <cstdint>

#define BATCH 8
#define MM 256
#define NN 256
#define CI 64
#define CO 64
#define KK 4
#define MODES 32

// ---------------- scratch ----------------
__device__ float2 g_wy [BATCH*MODES*CI*CO];
__device__ float2 g_wx [BATCH*MODES*CI*CO];
__device__ __half g_XfY[(size_t)BATCH*MODES*MM*CI*2];
__device__ __half g_XfX[(size_t)BATCH*MODES*NN*CI*2];
__device__ __half g_YfY[(size_t)BATCH*MODES*MM*CO*2];
__device__ __half g_YfX[(size_t)BATCH*MODES*NN*CO*2];
__device__ float  g_xsum2[(size_t)BATCH*MM*NN*CO];

#define W_W1   0
#define W_W2   36864
#define W_TOT  70656
__device__ __align__(16) unsigned char g_Wimg[W_TOT];

#define T_ST   528
#define T_TOT  33792
__device__ __align__(16) unsigned char g_TY[T_TOT];
__device__ __align__(16) unsigned char g_TX[T_TOT];
#define S_ST   144
#define S_TOT  36864
__device__ __align__(16) unsigned char g_SY[S_TOT];
__device__ __align__(16) unsigned char g_SX[S_TOT];

// ---------------- helpers ----------------
__device__ __forceinline__ uint32_t smem_u32(const void* p) {
    uint32_t a;
    asm("{ .reg .u64 t; cvta.to.shared.u64 t, %1; cvt.u32.u64 %0, t; }" : "=r"(a) : "l"(p));
    return a;
}
__device__ __forceinline__ void ldsm4(uint32_t* r, uint32_t a) {
    asm volatile("ldmatrix.sync.aligned.m8n8.x4.shared.b16 {%0,%1,%2,%3}, [%4];"
        : "=r"(r[0]), "=r"(r[1]), "=r"(r[2]), "=r"(r[3]) : "r"(a));
}
__device__ __forceinline__ void ldsm4t(uint32_t* r, uint32_t a) {
    asm volatile("ldmatrix.sync.aligned.m8n8.x4.trans.shared.b16 {%0,%1,%2,%3}, [%4];"
        : "=r"(r[0]), "=r"(r[1]), "=r"(r[2]), "=r"(r[3]) : "r"(a));
}
__device__ __forceinline__ uint32_t pk_h2(__half a, __half b) {
    __half2 t; t.x = a; t.y = b; return *(uint32_t*)&t;
}
__device__ __forceinline__ uint32_t cvt1_h(float v0, float v1) {
    return pk_h2(__float2half(v0), __float2half(v1));
}
__device__ __forceinline__ void cvt_pair_h(float v0, float v1, uint32_t& hi, uint32_t& lo) {
    __half h0 = __float2half(v0), h1 = __float2half(v1);
    float r0 = v0 - __half2float(h0);
    float r1 = v1 - __half2float(h1);
    hi = pk_h2(h0, h1);
    lo = pk_h2(__float2half(r0), __float2half(r1));
}
__device__ __forceinline__ void mma_f16(float* d, const uint32_t* a, uint32_t b0, uint32_t b1) {
    asm volatile(
        "mma.sync.aligned.m16n8k16.row.col.f32.f16.f16.f32 "
        "{%0,%1,%2,%3},{%4,%5,%6,%7},{%8,%9},{%0,%1,%2,%3};"
        : "+f"(d[0]), "+f"(d[1]), "+f"(d[2]), "+f"(d[3])
        : "r"(a[0]), "r"(a[1]), "r"(a[2]), "r"(a[3]), "r"(b0), "r"(b1));
}
__device__ __forceinline__ void wr_h(unsigned char* p, float v) {
    *(__half*)p = __float2half(v);
}

// ---------------- K0: merged prep (weights + W image + tables) ----------------
__global__ void k_prep(const float* __restrict__ att,
                       const float* __restrict__ fwy,
                       const float* __restrict__ fwx,
                       const float* __restrict__ w1,
                       const float* __restrict__ w2) {
    int bid = blockIdx.x;
    if (bid < 4096) {
        int gid = bid * 256 + threadIdx.x;
        int o = gid & 63, i = (gid >> 6) & 63, f = (gid >> 12) & 31, b = gid >> 17;
        float a0 = att[b*KK+0], a1 = att[b*KK+1], a2 = att[b*KK+2], a3 = att[b*KK+3];
        const int ks = CI*CO*MODES*2;
        int base = ((i*CO + o)*MODES + f)*2;
        float yr, yi, xr, xi;
        yr = a0*fwy[base   ] + a1*fwy[base+ks   ] + a2*fwy[base+2*ks  ] + a3*fwy[base+3*ks  ];
        yi = a0*fwy[base+1 ] + a1*fwy[base+ks+1 ] + a2*fwy[base+2*ks+1] + a3*fwy[base+3*ks+1];
        xr = a0*fwx[base   ] + a1*fwx[base+ks   ] + a2*fwx[base+2*ks  ] + a3*fwx[base+3*ks  ];
        xi = a0*fwx[base+1 ] + a1*fwx[base+ks+1 ] + a2*fwx[base+2*ks+1] + a3*fwx[base+3*ks+1];
        g_wy[gid] = make_float2(yr, yi);
        g_wx[gid] = make_float2(xr, xi);
    } else if (bid < 4224) {
        int gid = (bid - 4096) * 256 + threadIdx.x;
        if (gid < 16384) {
            int i = gid >> 8, j = gid & 255;
            wr_h(g_Wimg + W_W1 + (uint32_t)j*144 + (uint32_t)i*2, w1[gid]);
        } else {
            int idx = gid - 16384;
            int j = idx >> 6, o = idx & 63;
            wr_h(g_Wimg + W_W2 + (uint32_t)o*528 + (uint32_t)j*2, w2[idx]);
        }
    } else {
        int gid = (bid - 4224) * 256 + threadIdx.x;
        int sel = gid >> 14;
        int idx = gid & 16383;
        const float inv = 0.04428074428f;
        if (sel == 0) {
            int r = idx >> 8, k = idx & 255;
            int f = r >> 1;
            float ang = (float)((f*k) & 255) * (1.0f/128.0f);
            float v = (r & 1) ? -0.0625f*sinpif(ang) : 0.0625f*cospif(ang);
            wr_h(g_TY + (uint32_t)r*T_ST + (uint32_t)k*2, v);
        } else if (sel == 1) {
            int r = idx >> 8, k = idx & 255;
            int f = r >> 1;
            float v;
            if (r & 1) v = -2.0f*inv*sinpif((float)((f*k) % 510) * (1.0f/255.0f));
            else       v = (k == 0) ? inv : ((k == 255) ? ((f & 1) ? -inv : inv) : 0.0f);
            wr_h(g_TX + (uint32_t)r*T_ST + (uint32_t)k*2, v);
        } else if (sel == 2) {
            int r = idx >> 6, k = idx & 63;
            int f = k >> 1;
            float ang = (float)((f*r) & 255) * (1.0f/128.0f);
            float v = (k & 1) ? -0.125f*sinpif(ang)
                              : ((f == 0) ? 0.0625f : 0.125f)*cospif(ang);
            wr_h(g_SY + (uint32_t)r*S_ST + (uint32_t)k*2, v);
        } else {
            int r = idx >> 6, k = idx & 63;
            int f = k >> 1;
            float ang = (float)((f*r) % 510) * (1.0f/255.0f);
            float v = (k & 1) ? -2.0f*inv*sinpif(ang)
                              : ((f == 0) ? inv : 2.0f*inv)*cospif(ang);
            wr_h(g_SX + (uint32_t)r*S_ST + (uint32_t)k*2, v);
        }
    }
}

// ---------------- K1: forward transforms (fp16 out, 2 blocks/SM) ----------------
#define FW_B    33792
#define FW_TOT  70656
__global__ void __launch_bounds__(512, 2) k_fwd_mma(const float* __restrict__ x) {
    extern __shared__ __align__(16) unsigned char sm[];
    int t = threadIdx.x, w = t >> 5, l = t & 31, lq = l & 3;
    int z = blockIdx.x;
    int branch = z >> 8;
    int grp = z & 255;
    int b = grp >> 5, g = grp & 31;

    {
        const float4* src = (const float4*)(branch ? g_TX : g_TY);
        float4* dst = (float4*)sm;
        for (int i = t; i < T_TOT/16; i += 512) dst[i] = src[i];
    }

    int mt = w & 3, nh = w >> 2;
    uint32_t smb = smem_u32(sm);
    uint32_t aAddr = smb + (uint32_t)(mt*16 + (l & 15))*T_ST + (uint32_t)((l >> 4)*16);
    uint32_t bAddr = smb + FW_B
                   + (uint32_t)((l & 7) + ((l >> 3) & 1)*8)*144
                   + (uint32_t)(nh*32) + (uint32_t)((l >> 4)*16);
    __half* outb = branch ? g_XfX : g_XfY;

    float4 v[8];
    {
        int mn0 = g*8;
        #pragma unroll
        for (int it = 0; it < 8; it++) {
            int flat = it*512 + t;
            int c4 = flat & 15, k = flat >> 4;
            const float* p0;
            if (branch == 0) p0 = x + ((size_t)(b*256 + mn0))*16384 + (size_t)k*64 + c4*4;
            else             p0 = x + (((size_t)(b*256 + k))*256 + mn0)*64 + c4*4;
            v[it] = *(const float4*)p0;
        }
    }

    for (int it8 = 0; it8 < 8; it8++) {
        int mn = g*8 + it8;
        __syncthreads();
        #pragma unroll
        for (int it = 0; it < 8; it++) {
            int flat = it*512 + t;
            int c4 = flat & 15, k = flat >> 4;
            uint32_t h0 = cvt1_h(v[it].x, v[it].y);
            uint32_t h1 = cvt1_h(v[it].z, v[it].w);
            *(uint2*)(sm + FW_B + k*144 + c4*8) = make_uint2(h0, h1);
        }
        __syncthreads();

        if (it8 < 7) {
            int mn1 = mn + 1;
            #pragma unroll
            for (int it = 0; it < 8; it++) {
                int flat = it*512 + t;
                int c4 = flat & 15, k = flat >> 4;
                const float* p0;
                if (branch == 0) p0 = x + ((size_t)(b*256 + mn1))*16384 + (size_t)k*64 + c4*4;
                else             p0 = x + (((size_t)(b*256 + k))*256 + mn1)*64 + c4*4;
                v[it] = *(const float4*)p0;
            }
        }

        float c[2][4];
        #pragma unroll
        for (int j = 0; j < 2; j++)
            #pragma unroll
            for (int q = 0; q < 4; q++) c[j][q] = 0.f;

        #pragma unroll
        for (int kk = 0; kk < 16; kk++) {
            uint32_t ah[4], bh[4];
            ldsm4(ah, aAddr + kk*32);
            ldsm4t(bh, bAddr + kk*2304);
            mma_f16(c[0], ah, bh[0], bh[1]);
            mma_f16(c[1], ah, bh[2], bh[3]);
        }

        #pragma unroll
        for (int j = 0; j < 2; j++) {
            int ch = nh*16 + j*8 + 2*lq;
            int r0 = mt*16 + (l >> 2), r1 = r0 + 8;
            size_t base0 = ((size_t)(b*32 + (r0 >> 1))*256 + mn)*128 + ch*2 + (r0 & 1);
            size_t base1 = ((size_t)(b*32 + (r1 >> 1))*256 + mn)*128 + ch*2 + (r1 & 1);
            outb[base0]     = __float2half(c[j][0]);
            outb[base0 + 2] = __float2half(c[j][1]);
            outb[base1]     = __float2half(c[j][2]);
            outb[base1 + 2] = __float2half(c[j][3]);
        }
    }
}

// ---------------- K2: complex GEMM (2 blocks/SM) ----------------
#define MX_A   0
#define MX_W   69632
#define MX_TOT 104448

__global__ void __launch_bounds__(512, 2) k_mix_mma() {
    extern __shared__ __align__(16) unsigned char sm[];
    int t = threadIdx.x, w = t >> 5, l = t & 31, lq = l & 3;
    int z = blockIdx.x, branch = z >> 8, bf = z & 255;
    const __half* A = (branch ? g_XfX : g_XfY) + (size_t)bf*MM*128;
    const float2* W = (branch ? g_wx  : g_wy ) + (size_t)bf*CI*CO;
    __half*       C = (branch ? g_YfX : g_YfY) + (size_t)bf*MM*128;

    {
        const uint4* Af = (const uint4*)A;
        #pragma unroll
        for (int it = 0; it < 8; it++) {
            int ft = it*512 + t;
            int row = ft >> 4, q = ft & 15;
            *(uint4*)(sm + MX_A + row*272 + q*16) = Af[ft];
        }
    }
    {
        #pragma unroll
        for (int it = 0; it < 8; it++) {
            int flat = it*512 + t;
            int i = flat >> 6, o = flat & 63;
            float2 wv = W[flat];
            uint32_t ha = pk_h2(__float2half(wv.x), __float2half(-wv.y));
            uint32_t hb = pk_h2(__float2half(wv.y), __float2half(wv.x));
            *(uint32_t*)(sm + MX_W + (2*o  )*272 + i*4) = ha;
            *(uint32_t*)(sm + MX_W + (2*o+1)*272 + i*4) = hb;
        }
    }
    __syncthreads();

    uint32_t smb = smem_u32(sm);
    int m0 = w*16;
    uint32_t aAddr = smb + MX_A + (uint32_t)(m0 + (l & 15))*272 + (uint32_t)((l >> 4)*16);
    uint32_t bBase = smb + MX_W + (uint32_t)(((l >> 4)*8) + (l & 7))*272
                   + (uint32_t)(((l >> 3) & 1)*16);

    float acc[16][4];
    #pragma unroll
    for (int j2 = 0; j2 < 16; j2++)
        #pragma unroll
        for (int q = 0; q < 4; q++) acc[j2][q] = 0.f;

    #pragma unroll
    for (int kt = 0; kt < 8; kt++) {
        uint32_t ah[4];
        ldsm4(ah, aAddr + kt*32);
        #pragma unroll
        for (int u = 0; u < 8; u++) {
            uint32_t bh[4];
            ldsm4(bh, bBase + (uint32_t)(u*16)*272 + kt*32);
            mma_f16(acc[2*u  ], ah, bh[0], bh[1]);
            mma_f16(acc[2*u+1], ah, bh[2], bh[3]);
        }
    }

    #pragma unroll
    for (int j2 = 0; j2 < 16; j2++) {
        int row = m0 + (l >> 2);
        int col = j2*8 + 2*lq;
        *(uint32_t*)(C + (size_t)row*128 + col)     = cvt1_h(acc[j2][0], acc[j2][1]);
        *(uint32_t*)(C + (size_t)(row+8)*128 + col) = cvt1_h(acc[j2][2], acc[j2][3]);
    }
}

// ---------------- K3: inverse transform X (2 blocks/SM) -> g_xsum2 ----------------
#define IV_B   36864
#define IV_TOT 46080
__global__ void __launch_bounds__(512, 2) k_inv_mma() {
    extern __shared__ __align__(16) unsigned char sm[];
    int t = threadIdx.x, w = t >> 5, l = t & 31, lq = l & 3;
    int z = blockIdx.x;             // 256
    int b = z >> 5, g = z & 31;

    {
        const float4* src = (const float4*)g_SX;
        float4* dst = (float4*)sm;
        for (int i = t; i < S_TOT/16; i += 512) dst[i] = src[i];
    }

    uint32_t smb = smem_u32(sm);
    uint32_t aAddr = smb + (uint32_t)(w*16 + (l & 15))*S_ST + (uint32_t)((l >> 4)*16);
    uint32_t bBase = smb + IV_B
                   + (uint32_t)((l & 7) + ((l >> 3) & 1)*8)*144
                   + (uint32_t)((l >> 4)*16);
    const __half* Y = g_YfX;
    float* outb = g_xsum2;

    uint2 y[2];
    {
        int mn0 = g*8;
        #pragma unroll
        for (int it = 0; it < 2; it++) {
            int flat = it*512 + t;
            int f = flat >> 5, cp = flat & 31;
            y[it] = *(const uint2*)(Y + ((size_t)(b*32 + f)*256 + mn0)*128 + 4*cp);
        }
    }
    __syncthreads();

    uint32_t ah[4][4];
    #pragma unroll
    for (int kk = 0; kk < 4; kk++) ldsm4(ah[kk], aAddr + kk*32);

    for (int it8 = 0; it8 < 8; it8++) {
        int mn = g*8 + it8;
        if (it8 > 0) __syncthreads();
        #pragma unroll
        for (int it = 0; it < 2; it++) {
            int flat = it*512 + t;
            int f = flat >> 5, cp = flat & 31;
            uint32_t re = (y[it].x & 0xFFFFu) | (y[it].y << 16);
            uint32_t im = (y[it].x >> 16) | (y[it].y & 0xFFFF0000u);
            *(uint32_t*)(sm + IV_B + (2*f  )*144 + cp*4) = re;
            *(uint32_t*)(sm + IV_B + (2*f+1)*144 + cp*4) = im;
        }
        __syncthreads();

        if (it8 < 7) {
            int mn1 = mn + 1;
            #pragma unroll
            for (int it = 0; it < 2; it++) {
                int flat = it*512 + t;
                int f = flat >> 5, cp = flat & 31;
                y[it] = *(const uint2*)(Y + ((size_t)(b*32 + f)*256 + mn1)*128 + 4*cp);
            }
        }

        float c[8][4];
        #pragma unroll
        for (int j = 0; j < 8; j++)
            #pragma unroll
            for (int q = 0; q < 4; q++) c[j][q] = 0.f;

        #pragma unroll
        for (int kk = 0; kk < 4; kk++) {
            #pragma unroll
            for (int u = 0; u < 4; u++) {
                uint32_t bh[4];
                ldsm4t(bh, bBase + (uint32_t)(u*32) + (uint32_t)(kk*16)*144);
                mma_f16(c[2*u  ], ah[kk], bh[0], bh[1]);
                mma_f16(c[2*u+1], ah[kk], bh[2], bh[3]);
            }
        }

        #pragma unroll
        for (int j = 0; j < 8; j++) {
            int col = j*8 + 2*lq;
            int r0 = w*16 + (l >> 2), r1 = r0 + 8;
            size_t a0 = (((size_t)(b*256 + r0))*256 + mn)*64 + col;
            size_t a1 = (((size_t)(b*256 + r1))*256 + mn)*64 + col;
            *(float2*)(outb + a0) = make_float2(c[j][0], c[j][1]);
            *(float2*)(outb + a1) = make_float2(c[j][2], c[j][3]);
        }
    }
}

// ---------------- K4: fused inv-Y + MLP + LayerNorm (unchanged R16) ----------------
#define FM_SA_HI 0
#define FM_SA_LO 36864
#define FM_W     73728
#define FM_S     144384
#define FM_B     181248
#define FM_B1    190464
#define FM_B2    191488
#define FM_GAM   191744
#define FM_BET   192000
#define FM_TOT   192256

__global__ void __launch_bounds__(512) k_mlp_fused(const float* __restrict__ b1,
                                                   const float* __restrict__ b2,
                                                   const float* __restrict__ gamma,
                                                   const float* __restrict__ beta,
                                                   float* __restrict__ out) {
    extern __shared__ __align__(16) unsigned char sm[];
    int t = threadIdx.x;
    int w = t >> 5, l = t & 31;
    int lq = l & 3;
    int blk = blockIdx.x;

    {
        const float4* src = (const float4*)g_Wimg;
        float4* dst = (float4*)(sm + FM_W);
        for (int i = t; i < W_TOT/16; i += 512) dst[i] = src[i];
        const float4* src2 = (const float4*)g_SY;
        float4* dst2 = (float4*)(sm + FM_S);
        for (int i = t; i < S_TOT/16; i += 512) dst2[i] = src2[i];
    }
    float* b1s = (float*)(sm + FM_B1);
    float* b2s = (float*)(sm + FM_B2);
    float* gs  = (float*)(sm + FM_GAM);
    float* bs  = (float*)(sm + FM_BET);
    if (t < 256) b1s[t] = b1[t];
    if (t >= 256 && t < 320) { int q = t - 256; b2s[q] = b2[q]; gs[q] = gamma[q]; bs[q] = beta[q]; }

    uint32_t smb = smem_u32(sm);
    uint32_t sAAddr = smb + FM_S + (uint32_t)(w*16 + (l & 15))*S_ST + (uint32_t)((l >> 4)*16);
    uint32_t sBBase = smb + FM_B
                    + (uint32_t)((l & 7) + ((l >> 3) & 1)*8)*144
                    + (uint32_t)((l >> 4)*16);
    uint32_t aAddr  = smb + FM_SA_HI + (uint32_t)(w*16 + (l & 15))*144 + (uint32_t)((l >> 4)*16);
    uint32_t w1Base = smb + FM_W + W_W1
                    + (uint32_t)(((l >> 4)*8) + (l & 7))*144 + (uint32_t)(((l >> 3) & 1)*16);
    uint32_t w2Base = smb + FM_W + W_W2
                    + (uint32_t)(((l >> 4)*8) + (l & 7))*528 + (uint32_t)(((l >> 3) & 1)*16);

    uint2 y[2];
    {
        int tile0 = blk*4;
        int b = tile0 >> 8, m = tile0 & 255;
        #pragma unroll
        for (int it = 0; it < 2; it++) {
            int flat = it*512 + t;
            int f = flat >> 5, cp = flat & 31;
            y[it] = *(const uint2*)(g_YfY + ((size_t)(b*32 + f)*256 + m)*128 + 4*cp);
        }
    }
    __syncthreads();

    for (int tt4 = 0; tt4 < 4; tt4++) {
        int tile = blk*4 + tt4;
        if (tt4 > 0) __syncthreads();

        #pragma unroll
        for (int it = 0; it < 2; it++) {
            int flat = it*512 + t;
            int f = flat >> 5, cp = flat & 31;
            uint32_t re = (y[it].x & 0xFFFFu) | (y[it].y << 16);
            uint32_t im = (y[it].x >> 16) | (y[it].y & 0xFFFF0000u);
            *(uint32_t*)(sm + FM_B + (2*f  )*144 + cp*4) = re;
            *(uint32_t*)(sm + FM_B + (2*f+1)*144 + cp*4) = im;
        }
        __syncthreads();

        if (tt4 < 3) {
            int tileN = tile + 1;
            int bN = tileN >> 8, mN = tileN & 255;
            #pragma unroll
            for (int it = 0; it < 2; it++) {
                int flat = it*512 + t;
                int f = flat >> 5, cp = flat & 31;
                y[it] = *(const uint2*)(g_YfY + ((size_t)(bN*32 + f)*256 + mN)*128 + 4*cp);
            }
        }

        float ci[8][4];
        #pragma unroll
        for (int j = 0; j < 8; j++)
            #pragma unroll
            for (int q = 0; q < 4; q++) ci[j][q] = 0.f;

        #pragma unroll
        for (int kk = 0; kk < 4; kk++) {
            uint32_t ah[4];
            ldsm4(ah, sAAddr + kk*32);
            #pragma unroll
            for (int u = 0; u < 4; u++) {
                uint32_t bh[4];
                ldsm4t(bh, sBBase + (uint32_t)(u*32) + (uint32_t)(kk*16)*144);
                mma_f16(ci[2*u  ], ah, bh[0], bh[1]);
                mma_f16(ci[2*u+1], ah, bh[2], bh[3]);
            }
        }

        {
            size_t base = (size_t)tile * 256;
            int r0 = w*16 + (l >> 2), r1 = r0 + 8;
            #pragma unroll
            for (int j = 0; j < 8; j++) {
                int col = j*8 + 2*lq;
                float2 v0 = *(const float2*)(g_xsum2 + (base + r0)*64 + col);
                float2 v1 = *(const float2*)(g_xsum2 + (base + r1)*64 + col);
                v0.x += ci[j][0]; v0.y += ci[j][1];
                v1.x += ci[j][2]; v1.y += ci[j][3];
                uint32_t h0, l0, h1, l1;
                cvt_pair_h(v0.x, v0.y, h0, l0);
                cvt_pair_h(v1.x, v1.y, h1, l1);
                *(uint32_t*)(sm + FM_SA_HI + r0*144 + col*2) = h0;
                *(uint32_t*)(sm + FM_SA_LO + r0*144 + col*2) = l0;
                *(uint32_t*)(sm + FM_SA_HI + r1*144 + col*2) = h1;
                *(uint32_t*)(sm + FM_SA_LO + r1*144 + col*2) = l1;
            }
        }
        __syncthreads();

        float d2[8][4];
        #pragma unroll
        for (int j = 0; j < 8; j++)
            #pragma unroll
            for (int q = 0; q < 4; q++) d2[j][q] = 0.f;

        for (int cc = 0; cc < 4; cc++) {
            float h[8][4];
            #pragma unroll
            for (int j = 0; j < 8; j++)
                #pragma unroll
                for (int q = 0; q < 4; q++) h[j][q] = 0.f;

            #pragma unroll
            for (int kt = 0; kt < 4; kt++) {
                uint32_t ah[4], al[4];
                ldsm4(ah, aAddr + kt*32);
                ldsm4(al, aAddr + (FM_SA_LO - FM_SA_HI) + kt*32);
                #pragma unroll
                for (int u = 0; u < 4; u++) {
                    uint32_t bh[4];
                    ldsm4(bh, w1Base + (uint32_t)(cc*64 + u*16)*144 + kt*32);
                    mma_f16(h[2*u  ], ah, bh[0], bh[1]);
                    mma_f16(h[2*u  ], al, bh[0], bh[1]);
                    mma_f16(h[2*u+1], ah, bh[2], bh[3]);
                    mma_f16(h[2*u+1], al, bh[2], bh[3]);
                }
            }

            #pragma unroll
            for (int kt2 = 0; kt2 < 4; kt2++) {
                int j = 2*kt2;
                uint32_t ah2[4], al2[4];
                {
                    int g0 = cc*64 + j*8 + 2*lq;
                    float bA = b1s[g0],   bB = b1s[g0+1];
                    float bC = b1s[g0+8], bD = b1s[g0+9];
                    float v0 = fmaxf(h[j][0] + bA, 0.f);
                    float v1 = fmaxf(h[j][1] + bB, 0.f);
                    cvt_pair_h(v0, v1, ah2[0], al2[0]);
                    v0 = fmaxf(h[j][2] + bA, 0.f);
                    v1 = fmaxf(h[j][3] + bB, 0.f);
                    cvt_pair_h(v0, v1, ah2[1], al2[1]);
                    v0 = fmaxf(h[j+1][0] + bC, 0.f);
                    v1 = fmaxf(h[j+1][1] + bD, 0.f);
                    cvt_pair_h(v0, v1, ah2[2], al2[2]);
                    v0 = fmaxf(h[j+1][2] + bC, 0.f);
                    v1 = fmaxf(h[j+1][3] + bD, 0.f);
                    cvt_pair_h(v0, v1, ah2[3], al2[3]);
                }
                uint32_t kByte = (uint32_t)(cc*128 + kt2*32);
                #pragma unroll
                for (int u = 0; u < 4; u++) {
                    uint32_t bh[4];
                    ldsm4(bh, w2Base + (uint32_t)(u*16)*528 + kByte);
                    mma_f16(d2[2*u  ], ah2, bh[0], bh[1]);
                    mma_f16(d2[2*u  ], al2, bh[0], bh[1]);
                    mma_f16(d2[2*u+1], ah2, bh[2], bh[3]);
                    mma_f16(d2[2*u+1], al2, bh[2], bh[3]);
                }
            }
        }

        #pragma unroll
        for (int rh = 0; rh < 2; rh++) {
            float vals[16];
            #pragma unroll
            for (int j2 = 0; j2 < 8; j2++) {
                int col = j2*8 + 2*lq;
                vals[2*j2  ] = d2[j2][2*rh  ] + b2s[col];
                vals[2*j2+1] = d2[j2][2*rh+1] + b2s[col+1];
            }
            float s = 0.f;
            #pragma unroll
            for (int q = 0; q < 16; q++) s += vals[q];
            s += __shfl_xor_sync(0xffffffffu, s, 1);
            s += __shfl_xor_sync(0xffffffffu, s, 2);
            float mu = s * (1.f/64.f);
            float v = 0.f;
            #pragma unroll
            for (int q = 0; q < 16; q++) { float d = vals[q] - mu; v = fmaf(d, d, v); }
            v += __shfl_xor_sync(0xffffffffu, v, 1);
            v += __shfl_xor_sync(0xffffffffu, v, 2);
            float rinv = rsqrtf(v * (1.f/64.f) + 1e-5f);
            size_t row = (size_t)tile*256 + w*16 + rh*8 + (l >> 2);
            #pragma unroll
            for (int j2 = 0; j2 < 8; j2++) {
                int col = j2*8 + 2*lq;
                float2 r;
                r.x = (vals[2*j2  ] - mu) * rinv * gs[col  ] + bs[col  ];
                r.y = (vals[2*j2+1] - mu) * rinv * gs[col+1] + bs[col+1];
                *(float2*)(out + row*64 + col) = r;
            }
        }
    }
}

// ---------------- launcher ----------------
extern "C" void kernel_launch(void* const* d_in, const int* in_sizes, int n_in,
                              void* d_out, int out_size) {
    (void)in_sizes; (void)n_in; (void)out_size;
    const float* x     = (const float*)d_in[0];
    const float* att   = (const float*)d_in[1];
    const float* fwy   = (const float*)d_in[2];
    const float* fwx   = (const float*)d_in[3];
    const float* w1    = (const float*)d_in[4];
    const float* b1    = (const float*)d_in[5];
    const float* w2    = (const float*)d_in[6];
    const float* b2    = (const float*)d_in[7];
    const float* gamma = (const float*)d_in[8];
    const float* beta  = (const float*)d_in[9];
    float* out = (float*)d_out;

    cudaFuncSetAttribute(k_fwd_mma,  cudaFuncAttributeMaxDynamicSharedMemorySize, FW_TOT);
    cudaFuncSetAttribute(k_mix_mma,  cudaFuncAttributeMaxDynamicSharedMemorySize, MX_TOT);
    cudaFuncSetAttribute(k_inv_mma,  cudaFuncAttributeMaxDynamicSharedMemorySize, IV_TOT);
    cudaFuncSetAttribute(k_mlp_fused,cudaFuncAttributeMaxDynamicSharedMemorySize, FM_TOT);

    k_prep<<<4480, 256>>>(att, fwy, fwx, w1, w2);
    k_fwd_mma<<<512, 512, FW_TOT>>>(x);
    k_mix_mma<<<2*BATCH*MODES, 512, MX_TOT>>>();
    k_inv_mma<<<256, 512, IV_TOT>>>();
    k_mlp_fused<<<512, 512, FM_TOT>>>(b1, b2, gamma, beta, out);
}